// round 15
// baseline (speedup 1.0000x reference)
#include <cuda_runtime.h>
#include <cuda_fp16.h>
#include <cstdint>

#define B_DIM 8
#define T_DIM 2048
#define D_DIM 2048
#define M_DIM (B_DIM * T_DIM)   // 16384

// ---------------- device-global scratch (static, allowed) -------------------
__device__ __align__(256) __half g_Ph[(size_t)M_DIM * D_DIM];  // (x@Wp^T+bp)/6, fp16
__device__ __align__(256) __half g_A [(size_t)M_DIM * D_DIM];  // fp16(x)
__device__ __align__(256) __half g_B [(size_t)D_DIM * D_DIM];  // fp16(Wp)

// ---------------- helpers ----------------------------------------------------
__device__ __forceinline__ uint32_t smem_u32(const void* p) {
    uint32_t a;
    asm("{ .reg .u64 t; cvta.to.shared.u64 t, %1; cvt.u32.u64 %0, t; }" : "=r"(a) : "l"(p));
    return a;
}
__device__ __forceinline__ void cp16(uint32_t sdst, const void* gsrc) {
    asm volatile("cp.async.cg.shared.global [%0], [%1], 16;" :: "r"(sdst), "l"(gsrc));
}
__device__ __forceinline__ uint32_t sw128(uint32_t o) { return o ^ ((o >> 3) & 0x70); }

__device__ __forceinline__ void ldmatrix_x4(uint32_t* f, uint32_t addr) {
    asm volatile("ldmatrix.sync.aligned.m8n8.x4.shared.b16 {%0,%1,%2,%3}, [%4];"
                 : "=r"(f[0]), "=r"(f[1]), "=r"(f[2]), "=r"(f[3]) : "r"(addr));
}
__device__ __forceinline__ void mma16816(float* c, const uint32_t* a,
                                         uint32_t b0, uint32_t b1) {
    asm volatile(
        "mma.sync.aligned.m16n8k16.row.col.f32.f16.f16.f32 "
        "{%0,%1,%2,%3}, {%4,%5,%6,%7}, {%8,%9}, {%0,%1,%2,%3};"
        : "+f"(c[0]), "+f"(c[1]), "+f"(c[2]), "+f"(c[3])
        : "r"(a[0]), "r"(a[1]), "r"(a[2]), "r"(a[3]), "r"(b0), "r"(b1));
}

// ---------------- fp32 -> fp16 convert (x and Wp, 8 elems/thread) ------------
__global__ __launch_bounds__(256) void cvt_fp16_kernel(
    const float4* __restrict__ xs, const float4* __restrict__ ws,
    uint4* __restrict__ da, uint4* __restrict__ db, int nx8, int ntot8) {
    int i = blockIdx.x * 256 + threadIdx.x;
    if (i >= ntot8) return;
    const bool isx = (i < nx8);
    const float4* src = isx ? (xs + 2 * (size_t)i) : (ws + 2 * (size_t)(i - nx8));
    const float4 v0 = src[0];
    const float4 v1 = src[1];
    __half2 h0 = __floats2half2_rn(v0.x, v0.y);
    __half2 h1 = __floats2half2_rn(v0.z, v0.w);
    __half2 h2 = __floats2half2_rn(v1.x, v1.y);
    __half2 h3 = __floats2half2_rn(v1.z, v1.w);
    uint4 o = make_uint4(*reinterpret_cast<const uint32_t*>(&h0),
                         *reinterpret_cast<const uint32_t*>(&h1),
                         *reinterpret_cast<const uint32_t*>(&h2),
                         *reinterpret_cast<const uint32_t*>(&h3));
    if (isx) da[i] = o; else db[i - nx8] = o;
}

// ---------------- HMMA GEMM (R14 proven, untouched) --------------------------
namespace hg {
constexpr int BM = 128, BN = 128, BK = 64, STAGES = 3;
constexpr int NKT = D_DIM / BK;                 // 32
constexpr int TILE_A = BM * 128;                // 16 KB
constexpr int TILE_B = BN * 128;                // 16 KB
constexpr int SMEM_BYTES = STAGES * (TILE_A + TILE_B) + 1024;  // 99328
}

__global__ __launch_bounds__(128, 2) void gemm_hmma_kernel(const float* __restrict__ bias) {
    using namespace hg;
    extern __shared__ char smem_raw[];
    const uint32_t sbase = (smem_u32(smem_raw) + 1023u) & ~1023u;
    const uint32_t bbase = sbase + STAGES * TILE_A;

    const int tid  = threadIdx.x;
    const int wid  = tid >> 5;
    const int lane = tid & 31;
    const int brow = blockIdx.y * BM;
    const int bcol = blockIdx.x * BN;
    const int wm = wid & 1;
    const int wn = wid >> 1;

    const __half* Ag = g_A + (size_t)brow * D_DIM;
    const __half* Bg = g_B + (size_t)bcol * D_DIM;

    const int lrow = tid >> 3;   // 0..15
    const int lseg = tid & 7;

    auto load_stage = [&](int s, int k0) {
        const uint32_t a_s = sbase + s * TILE_A;
        const uint32_t b_s = bbase + s * TILE_B;
#pragma unroll
        for (int p = 0; p < 8; p++) {
            const int row = lrow + p * 16;
            const uint32_t off = sw128((uint32_t)(row * 128 + lseg * 16));
            const size_t gofs = (size_t)row * D_DIM + k0 + lseg * 8;
            cp16(a_s + off, Ag + gofs);
            cp16(b_s + off, Bg + gofs);
        }
    };

    const int a_r_base = wm * 64 + (lane & 15);
    const int ab_cb    = ((lane >> 4) << 4);
    const int b_r_base = wn * 64 + (lane & 7) + ((lane >> 3) & 1) * 8;

    auto load_frags = [&](uint32_t (&af)[4][4], uint32_t (&bf)[4][4],
                          int s, int kb) {
        const uint32_t a_s = sbase + s * TILE_A;
        const uint32_t b_s = bbase + s * TILE_B;
#pragma unroll
        for (int i = 0; i < 4; i++)
            ldmatrix_x4(af[i], a_s + sw128((uint32_t)((a_r_base + i * 16) * 128 + kb + ab_cb)));
#pragma unroll
        for (int j = 0; j < 4; j++)
            ldmatrix_x4(bf[j], b_s + sw128((uint32_t)((b_r_base + j * 16) * 128 + kb + ab_cb)));
    };

    float acc[4][8][4];
#pragma unroll
    for (int i = 0; i < 4; i++)
#pragma unroll
        for (int j = 0; j < 8; j++)
#pragma unroll
            for (int e = 0; e < 4; e++) acc[i][j][e] = 0.0f;

    auto mma_all = [&](uint32_t (&af)[4][4], uint32_t (&bf)[4][4]) {
#pragma unroll
        for (int i = 0; i < 4; i++)
#pragma unroll
            for (int j = 0; j < 4; j++) {
                mma16816(acc[i][2 * j],     af[i], bf[j][0], bf[j][2]);
                mma16816(acc[i][2 * j + 1], af[i], bf[j][1], bf[j][3]);
            }
    };

    load_stage(0, 0);
    asm volatile("cp.async.commit_group;" ::: "memory");
    load_stage(1, BK);
    asm volatile("cp.async.commit_group;" ::: "memory");
    asm volatile("cp.async.wait_group 1;" ::: "memory");
    __syncthreads();

    uint32_t af[2][4][4], bf[2][4][4];
    load_frags(af[0], bf[0], 0, 0);

#define KT_BODY(S, SLD, SNXT, KT)                                             \
    {                                                                         \
        const int pf = (KT) + 2;                                              \
        if (pf < NKT) load_stage((SLD), pf * BK);                             \
        asm volatile("cp.async.commit_group;" ::: "memory");                  \
        _Pragma("unroll")                                                     \
        for (int kk = 0; kk < BK / 16; kk++) {                                \
            const int cur = kk & 1, nxt = cur ^ 1;                            \
            if (kk < 3) {                                                     \
                load_frags(af[nxt], bf[nxt], (S), (kk + 1) * 32);             \
            } else if ((KT) + 1 < NKT) {                                      \
                asm volatile("cp.async.wait_group 1;" ::: "memory");          \
                load_frags(af[nxt], bf[nxt], (SNXT), 0);                      \
            }                                                                 \
            mma_all(af[cur], bf[cur]);                                        \
        }                                                                     \
        __syncthreads();                                                      \
    }

#pragma unroll 1
    for (int ktg = 0; ktg < NKT - 2; ktg += 3) {
        KT_BODY(0, 2, 1, ktg);
        KT_BODY(1, 0, 2, ktg + 1);
        KT_BODY(2, 1, 0, ktg + 2);
    }
    KT_BODY(0, 2, 1, NKT - 2);
    KT_BODY(1, 0, 2, NKT - 1);
#undef KT_BODY

    const float inv6 = 1.0f / 6.0f;
    const int prow0 = brow + wm * 64 + (lane >> 2);
    const int pcol0 = bcol + wn * 64 + (lane & 3) * 2;
#pragma unroll
    for (int i = 0; i < 4; i++) {
        const size_t r0 = (size_t)(prow0 + i * 16);
#pragma unroll
        for (int j = 0; j < 8; j++) {
            const int c = pcol0 + j * 8;
            const float b0 = bias[c], b1 = bias[c + 1];
            __half2 lo = __floats2half2_rn((acc[i][j][0] + b0) * inv6,
                                           (acc[i][j][1] + b1) * inv6);
            __half2 hi = __floats2half2_rn((acc[i][j][2] + b0) * inv6,
                                           (acc[i][j][3] + b1) * inv6);
            *reinterpret_cast<__half2*>(&g_Ph[r0 * D_DIM + c])       = lo;
            *reinterpret_cast<__half2*>(&g_Ph[(r0 + 8) * D_DIM + c]) = hi;
        }
    }
}

// ---------------- fused chained LayerNorm: 2 rows per CTA, interleaved -------
// Rows (2b, 2b+1). t0 is even (T even) so t0 <= T-2 always; t1 = t0+1 >= 1.
// Uniform barrier path: edge rows (t0==0 / t1==T-1) run phase 2 as identity.
__device__ __forceinline__ float4 block_sum4(float a0, float b0, float a1, float b1) {
    __shared__ float sm[32];
    const int lane = threadIdx.x & 31;
    const int wid  = threadIdx.x >> 5;
#pragma unroll
    for (int o = 16; o > 0; o >>= 1) {
        a0 += __shfl_xor_sync(0xffffffffu, a0, o);
        b0 += __shfl_xor_sync(0xffffffffu, b0, o);
        a1 += __shfl_xor_sync(0xffffffffu, a1, o);
        b1 += __shfl_xor_sync(0xffffffffu, b1, o);
    }
    __syncthreads();   // protect sm against previous call's readers
    if (lane == 0) {
        sm[wid] = a0; sm[8 + wid] = b0; sm[16 + wid] = a1; sm[24 + wid] = b1;
    }
    __syncthreads();
    float s0 = 0.0f, q0 = 0.0f, s1 = 0.0f, q1 = 0.0f;
#pragma unroll
    for (int i = 0; i < 8; i++) {
        s0 += sm[i]; q0 += sm[8 + i]; s1 += sm[16 + i]; q1 += sm[24 + i];
    }
    return make_float4(s0, q0, s1, q1);
}

__global__ __launch_bounds__(256) void ln_fuse2_kernel(
    const float* __restrict__ x, const float* __restrict__ gamma,
    const float* __restrict__ beta, float* __restrict__ out) {
    const int r0  = blockIdx.x * 2;
    const int r1  = r0 + 1;
    const int t0  = r0 & (T_DIM - 1);      // even
    const int tid = threadIdx.x;
    const float invD = 1.0f / (float)D_DIM;
    constexpr int DP = D_DIM / 2;

    const float2*  xr0 = (const float2*)x + (size_t)r0 * DP;
    const float2*  xr1 = (const float2*)x + (size_t)r1 * DP;
    const int p1r0 = (t0 == 0) ? r1 : (r0 - 1);
    const __half2* p10 = (const __half2*)g_Ph + (size_t)p1r0 * DP;
    const __half2* p11 = (const __half2*)g_Ph + (size_t)r0 * DP;   // r1-1 = r0
    const float2*  g2  = (const float2*)gamma;
    const float2*  b2  = (const float2*)beta;

    // ---------------- phase 1: v = x + P[prev]; joint stats ----------------
    float2 v0[4], v1[4];
    float s0 = 0.0f, q0 = 0.0f, s1 = 0.0f, q1 = 0.0f;
#pragma unroll
    for (int i = 0; i < 4; i++) {
        const int q = i * 256 + tid;
        const float2 xa = xr0[q];
        const float2 xb = xr1[q];
        const float2 pa = __half22float2(p10[q]);
        const float2 pb = __half22float2(p11[q]);
        const float a0 = xa.x + pa.x, b0v = xa.y + pa.y;
        const float a1 = xb.x + pb.x, b1v = xb.y + pb.y;
        v0[i] = make_float2(a0, b0v);
        v1[i] = make_float2(a1, b1v);
        s0 += a0 + b0v; q0 += a0 * a0 + b0v * b0v;
        s1 += a1 + b1v; q1 += a1 * a1 + b1v * b1v;
    }
    float4 red = block_sum4(s0, q0, s1, q1);
    float mean0 = red.x * invD, mean1 = red.z * invD;
    float rstd0 = rsqrtf(red.y * invD - mean0 * mean0 + 1e-5f);
    float rstd1 = rsqrtf(red.w * invD - mean1 * mean1 + 1e-5f);

    // ---------------- phase 2: v = LN1(v) + P[next] (identity on edge rows) --
    const bool n0 = (t0 >= 1);              // row0 interior (t0 <= T-2 always)
    const bool n1 = (t0 + 1 <= T_DIM - 2);  // row1 interior (t1 >= 1 always)
    const __half2* p20 = (const __half2*)g_Ph + (size_t)r1 * DP;        // r0+1
    const __half2* p21 = (const __half2*)g_Ph + (size_t)(r1 + 1) * DP;  // valid iff n1

    float2 gg[4], bb[4];
    s0 = 0.0f; q0 = 0.0f; s1 = 0.0f; q1 = 0.0f;
#pragma unroll
    for (int i = 0; i < 4; i++) {
        const int q = i * 256 + tid;
        gg[i] = g2[q]; bb[i] = b2[q];
        if (n0) {
            const float2 pv = __half22float2(p20[q]);
            v0[i].x = (v0[i].x - mean0) * rstd0 * gg[i].x + bb[i].x + pv.x;
            v0[i].y = (v0[i].y - mean0) * rstd0 * gg[i].y + bb[i].y + pv.y;
        }
        if (n1) {
            const float2 pv = __half22float2(p21[q]);
            v1[i].x = (v1[i].x - mean1) * rstd1 * gg[i].x + bb[i].x + pv.x;
            v1[i].y = (v1[i].y - mean1) * rstd1 * gg[i].y + bb[i].y + pv.y;
        }
        s0 += v0[i].x + v0[i].y; q0 += v0[i].x * v0[i].x + v0[i].y * v0[i].y;
        s1 += v1[i].x + v1[i].y; q1 += v1[i].x * v1[i].x + v1[i].y * v1[i].y;
    }
    red   = block_sum4(s0, q0, s1, q1);
    mean0 = red.x * invD; mean1 = red.z * invD;
    rstd0 = rsqrtf(red.y * invD - mean0 * mean0 + 1e-5f);
    rstd1 = rsqrtf(red.w * invD - mean1 * mean1 + 1e-5f);

    // ---------------- phase 3: final LN + store ------------------------------
    float2* o0 = (float2*)out + (size_t)r0 * DP;
    float2* o1 = (float2*)out + (size_t)r1 * DP;
#pragma unroll
    for (int i = 0; i < 4; i++) {
        const int q = i * 256 + tid;
        o0[q] = make_float2((v0[i].x - mean0) * rstd0 * gg[i].x + bb[i].x,
                            (v0[i].y - mean0) * rstd0 * gg[i].y + bb[i].y);
        o1[q] = make_float2((v1[i].x - mean1) * rstd1 * gg[i].x + bb[i].x,
                            (v1[i].y - mean1) * rstd1 * gg[i].y + bb[i].y);
    }
}

// ---------------- launch ------------------------------------------------------
extern "C" void kernel_launch(void* const* d_in, const int* in_sizes, int n_in,
                              void* d_out, int out_size) {
    const float* x     = (const float*)d_in[0];
    const float* Wp    = (const float*)d_in[5];
    const float* bp    = (const float*)d_in[6];
    const float* gamma = (const float*)d_in[7];
    const float* beta  = (const float*)d_in[8];
    float* out = (float*)d_out;

    static bool attr_set = false;
    if (!attr_set) {
        cudaFuncSetAttribute(gemm_hmma_kernel,
                             cudaFuncAttributeMaxDynamicSharedMemorySize, hg::SMEM_BYTES);
        attr_set = true;
    }

    __half* gA; cudaGetSymbolAddress((void**)&gA, g_A);
    __half* gB; cudaGetSymbolAddress((void**)&gB, g_B);

    const int nx8  = M_DIM * D_DIM / 8;
    const int nw8  = D_DIM * D_DIM / 8;
    const int ntot = nx8 + nw8;
    cvt_fp16_kernel<<<(ntot + 255) / 256, 256>>>(
        (const float4*)x, (const float4*)Wp, (uint4*)gA, (uint4*)gB, nx8, ntot);

    dim3 ggrid(D_DIM / hg::BN, M_DIM / hg::BM);   // (16, 128)
    gemm_hmma_kernel<<<ggrid, 128, hg::SMEM_BYTES>>>(bp);

    ln_fuse2_kernel<<<M_DIM / 2, 256>>>(x, gamma, beta, out);
}

// round 16
// speedup vs baseline: 1.0441x; 1.0441x over previous
#include <cuda_runtime.h>
#include <cuda_fp16.h>
#include <cstdint>

#define B_DIM 8
#define T_DIM 2048
#define D_DIM 2048
#define M_DIM (B_DIM * T_DIM)   // 16384

// Wave-aligned split: 148 SMs x 2 CTAs = 296 slots; 74*16 = 1184 = 4 waves.
#define YBLK_LO 74
#define YBLK_HI (128 - YBLK_LO)           // 54
#define R_LO    (YBLK_LO * 128)           // 9472 rows in gemm_lo
#define LN_LO   (R_LO - 1)                // 9471 rows safe with P < R_LO
#define LN_HI   (M_DIM - LN_LO)           // 6913

// ---------------- device-global scratch (static, allowed) -------------------
__device__ __align__(256) __half g_Ph[(size_t)M_DIM * D_DIM];  // (x@Wp^T+bp)/6, fp16
__device__ __align__(256) __half g_A [(size_t)M_DIM * D_DIM];  // fp16(x)
__device__ __align__(256) __half g_B [(size_t)D_DIM * D_DIM];  // fp16(Wp)

// ---------------- helpers ----------------------------------------------------
__device__ __forceinline__ uint32_t smem_u32(const void* p) {
    uint32_t a;
    asm("{ .reg .u64 t; cvta.to.shared.u64 t, %1; cvt.u32.u64 %0, t; }" : "=r"(a) : "l"(p));
    return a;
}
__device__ __forceinline__ void cp16(uint32_t sdst, const void* gsrc) {
    asm volatile("cp.async.cg.shared.global [%0], [%1], 16;" :: "r"(sdst), "l"(gsrc));
}
__device__ __forceinline__ uint32_t sw128(uint32_t o) { return o ^ ((o >> 3) & 0x70); }

__device__ __forceinline__ void ldmatrix_x4(uint32_t* f, uint32_t addr) {
    asm volatile("ldmatrix.sync.aligned.m8n8.x4.shared.b16 {%0,%1,%2,%3}, [%4];"
                 : "=r"(f[0]), "=r"(f[1]), "=r"(f[2]), "=r"(f[3]) : "r"(addr));
}
__device__ __forceinline__ void mma16816(float* c, const uint32_t* a,
                                         uint32_t b0, uint32_t b1) {
    asm volatile(
        "mma.sync.aligned.m16n8k16.row.col.f32.f16.f16.f32 "
        "{%0,%1,%2,%3}, {%4,%5,%6,%7}, {%8,%9}, {%0,%1,%2,%3};"
        : "+f"(c[0]), "+f"(c[1]), "+f"(c[2]), "+f"(c[3])
        : "r"(a[0]), "r"(a[1]), "r"(a[2]), "r"(a[3]), "r"(b0), "r"(b1));
}

// ---------------- fp32 -> fp16 converts --------------------------------------
// lo: x rows [0, R_LO) plus all of Wp (one fused launch)
__global__ __launch_bounds__(256) void cvt_fp16_kernel(
    const float4* __restrict__ xs, const float4* __restrict__ ws,
    uint4* __restrict__ da, uint4* __restrict__ db, int nx8, int ntot8) {
    int i = blockIdx.x * 256 + threadIdx.x;
    if (i >= ntot8) return;
    const bool isx = (i < nx8);
    const float4* src = isx ? (xs + 2 * (size_t)i) : (ws + 2 * (size_t)(i - nx8));
    const float4 v0 = src[0];
    const float4 v1 = src[1];
    __half2 h0 = __floats2half2_rn(v0.x, v0.y);
    __half2 h1 = __floats2half2_rn(v0.z, v0.w);
    __half2 h2 = __floats2half2_rn(v1.x, v1.y);
    __half2 h3 = __floats2half2_rn(v1.z, v1.w);
    uint4 o = make_uint4(*reinterpret_cast<const uint32_t*>(&h0),
                         *reinterpret_cast<const uint32_t*>(&h1),
                         *reinterpret_cast<const uint32_t*>(&h2),
                         *reinterpret_cast<const uint32_t*>(&h3));
    if (isx) da[i] = o; else db[i - nx8] = o;
}

// hi: x rows [R_LO, M_DIM) only
__global__ __launch_bounds__(256) void cvt_x_range_kernel(
    const float4* __restrict__ xs, uint4* __restrict__ da, int n8) {
    int i = blockIdx.x * 256 + threadIdx.x;
    if (i >= n8) return;
    const float4 v0 = xs[2 * (size_t)i];
    const float4 v1 = xs[2 * (size_t)i + 1];
    __half2 h0 = __floats2half2_rn(v0.x, v0.y);
    __half2 h1 = __floats2half2_rn(v0.z, v0.w);
    __half2 h2 = __floats2half2_rn(v1.x, v1.y);
    __half2 h3 = __floats2half2_rn(v1.z, v1.w);
    da[i] = make_uint4(*reinterpret_cast<const uint32_t*>(&h0),
                       *reinterpret_cast<const uint32_t*>(&h1),
                       *reinterpret_cast<const uint32_t*>(&h2),
                       *reinterpret_cast<const uint32_t*>(&h3));
}

// ---------------- HMMA GEMM (R14 proven schedule + y-offset) -----------------
namespace hg {
constexpr int BM = 128, BN = 128, BK = 64, STAGES = 3;
constexpr int NKT = D_DIM / BK;                 // 32
constexpr int TILE_A = BM * 128;                // 16 KB
constexpr int TILE_B = BN * 128;                // 16 KB
constexpr int SMEM_BYTES = STAGES * (TILE_A + TILE_B) + 1024;  // 99328
}

__global__ __launch_bounds__(128, 2) void gemm_hmma_kernel(
    const float* __restrict__ bias, int y0) {
    using namespace hg;
    extern __shared__ char smem_raw[];
    const uint32_t sbase = (smem_u32(smem_raw) + 1023u) & ~1023u;
    const uint32_t bbase = sbase + STAGES * TILE_A;

    const int tid  = threadIdx.x;
    const int wid  = tid >> 5;
    const int lane = tid & 31;
    const int brow = (blockIdx.y + y0) * BM;
    const int bcol = blockIdx.x * BN;
    const int wm = wid & 1;
    const int wn = wid >> 1;

    const __half* Ag = g_A + (size_t)brow * D_DIM;
    const __half* Bg = g_B + (size_t)bcol * D_DIM;

    const int lrow = tid >> 3;   // 0..15
    const int lseg = tid & 7;

    auto load_stage = [&](int s, int k0) {
        const uint32_t a_s = sbase + s * TILE_A;
        const uint32_t b_s = bbase + s * TILE_B;
#pragma unroll
        for (int p = 0; p < 8; p++) {
            const int row = lrow + p * 16;
            const uint32_t off = sw128((uint32_t)(row * 128 + lseg * 16));
            const size_t gofs = (size_t)row * D_DIM + k0 + lseg * 8;
            cp16(a_s + off, Ag + gofs);
            cp16(b_s + off, Bg + gofs);
        }
    };

    const int a_r_base = wm * 64 + (lane & 15);
    const int ab_cb    = ((lane >> 4) << 4);
    const int b_r_base = wn * 64 + (lane & 7) + ((lane >> 3) & 1) * 8;

    auto load_frags = [&](uint32_t (&af)[4][4], uint32_t (&bf)[4][4],
                          int s, int kb) {
        const uint32_t a_s = sbase + s * TILE_A;
        const uint32_t b_s = bbase + s * TILE_B;
#pragma unroll
        for (int i = 0; i < 4; i++)
            ldmatrix_x4(af[i], a_s + sw128((uint32_t)((a_r_base + i * 16) * 128 + kb + ab_cb)));
#pragma unroll
        for (int j = 0; j < 4; j++)
            ldmatrix_x4(bf[j], b_s + sw128((uint32_t)((b_r_base + j * 16) * 128 + kb + ab_cb)));
    };

    float acc[4][8][4];
#pragma unroll
    for (int i = 0; i < 4; i++)
#pragma unroll
        for (int j = 0; j < 8; j++)
#pragma unroll
            for (int e = 0; e < 4; e++) acc[i][j][e] = 0.0f;

    auto mma_all = [&](uint32_t (&af)[4][4], uint32_t (&bf)[4][4]) {
#pragma unroll
        for (int i = 0; i < 4; i++)
#pragma unroll
            for (int j = 0; j < 4; j++) {
                mma16816(acc[i][2 * j],     af[i], bf[j][0], bf[j][2]);
                mma16816(acc[i][2 * j + 1], af[i], bf[j][1], bf[j][3]);
            }
    };

    load_stage(0, 0);
    asm volatile("cp.async.commit_group;" ::: "memory");
    load_stage(1, BK);
    asm volatile("cp.async.commit_group;" ::: "memory");
    asm volatile("cp.async.wait_group 1;" ::: "memory");
    __syncthreads();

    uint32_t af[2][4][4], bf[2][4][4];
    load_frags(af[0], bf[0], 0, 0);

#define KT_BODY(S, SLD, SNXT, KT)                                             \
    {                                                                         \
        const int pf = (KT) + 2;                                              \
        if (pf < NKT) load_stage((SLD), pf * BK);                             \
        asm volatile("cp.async.commit_group;" ::: "memory");                  \
        _Pragma("unroll")                                                     \
        for (int kk = 0; kk < BK / 16; kk++) {                                \
            const int cur = kk & 1, nxt = cur ^ 1;                            \
            if (kk < 3) {                                                     \
                load_frags(af[nxt], bf[nxt], (S), (kk + 1) * 32);             \
            } else if ((KT) + 1 < NKT) {                                      \
                asm volatile("cp.async.wait_group 1;" ::: "memory");          \
                load_frags(af[nxt], bf[nxt], (SNXT), 0);                      \
            }                                                                 \
            mma_all(af[cur], bf[cur]);                                        \
        }                                                                     \
        __syncthreads();                                                      \
    }

#pragma unroll 1
    for (int ktg = 0; ktg < NKT - 2; ktg += 3) {
        KT_BODY(0, 2, 1, ktg);
        KT_BODY(1, 0, 2, ktg + 1);
        KT_BODY(2, 1, 0, ktg + 2);
    }
    KT_BODY(0, 2, 1, NKT - 2);
    KT_BODY(1, 0, 2, NKT - 1);
#undef KT_BODY

    const float inv6 = 1.0f / 6.0f;
    const int prow0 = brow + wm * 64 + (lane >> 2);
    const int pcol0 = bcol + wn * 64 + (lane & 3) * 2;
#pragma unroll
    for (int i = 0; i < 4; i++) {
        const size_t r0 = (size_t)(prow0 + i * 16);
#pragma unroll
        for (int j = 0; j < 8; j++) {
            const int c = pcol0 + j * 8;
            const float b0 = bias[c], b1 = bias[c + 1];
            __half2 lo = __floats2half2_rn((acc[i][j][0] + b0) * inv6,
                                           (acc[i][j][1] + b1) * inv6);
            __half2 hi = __floats2half2_rn((acc[i][j][2] + b0) * inv6,
                                           (acc[i][j][3] + b1) * inv6);
            *reinterpret_cast<__half2*>(&g_Ph[r0 * D_DIM + c])       = lo;
            *reinterpret_cast<__half2*>(&g_Ph[(r0 + 8) * D_DIM + c]) = hi;
        }
    }
}

// ---------------- fused chained LayerNorm (R14 proven + row offset) ----------
__device__ __forceinline__ float2 block_sum2(float a, float b) {
    __shared__ float sm[16];
    const int lane = threadIdx.x & 31;
    const int wid  = threadIdx.x >> 5;
#pragma unroll
    for (int o = 16; o > 0; o >>= 1) {
        a += __shfl_xor_sync(0xffffffffu, a, o);
        b += __shfl_xor_sync(0xffffffffu, b, o);
    }
    __syncthreads();
    if (lane == 0) { sm[wid] = a; sm[8 + wid] = b; }
    __syncthreads();
    float sa = 0.0f, sb = 0.0f;
#pragma unroll
    for (int i = 0; i < 8; i++) { sa += sm[i]; sb += sm[8 + i]; }
    return make_float2(sa, sb);
}

__global__ __launch_bounds__(256) void ln_fuse_kernel(
    const float* __restrict__ x, const float* __restrict__ gamma,
    const float* __restrict__ beta, float* __restrict__ out, int r0) {
    const int r   = blockIdx.x + r0;
    const int t   = r & (T_DIM - 1);
    const int tid = threadIdx.x;
    const float invD = 1.0f / (float)D_DIM;
    constexpr int DP = D_DIM / 2;

    const float2*  xr = (const float2*)x + (size_t)r * DP;
    const int p1row   = (t == 0) ? (r + 1) : (r - 1);
    const __half2* p1 = (const __half2*)g_Ph + (size_t)p1row * DP;
    const float2*  g2 = (const float2*)gamma;
    const float2*  b2 = (const float2*)beta;

    float2 v[4];
    float s = 0.0f, sq = 0.0f;
#pragma unroll
    for (int i = 0; i < 4; i++) {
        const int q = i * 256 + tid;
        const float2 xv = xr[q];
        const float2 pv = __half22float2(p1[q]);
        const float a = xv.x + pv.x, b = xv.y + pv.y;
        v[i] = make_float2(a, b);
        s += a + b; sq += a * a + b * b;
    }
    float2 red = block_sum2(s, sq);
    float mean = red.x * invD;
    float var  = red.y * invD - mean * mean;
    float rstd = rsqrtf(var + 1e-5f);

    if (t >= 1 && t <= T_DIM - 2) {
        const __half2* p2 = (const __half2*)g_Ph + (size_t)(r + 1) * DP;
        s = 0.0f; sq = 0.0f;
#pragma unroll
        for (int i = 0; i < 4; i++) {
            const int q = i * 256 + tid;
            const float2 gg = g2[q], bb = b2[q];
            const float2 pv = __half22float2(p2[q]);
            const float a = (v[i].x - mean) * rstd * gg.x + bb.x + pv.x;
            const float b = (v[i].y - mean) * rstd * gg.y + bb.y + pv.y;
            v[i] = make_float2(a, b);
            s += a + b; sq += a * a + b * b;
        }
        red  = block_sum2(s, sq);
        mean = red.x * invD;
        var  = red.y * invD - mean * mean;
        rstd = rsqrtf(var + 1e-5f);
    }

    float2* orow = (float2*)out + (size_t)r * DP;
#pragma unroll
    for (int i = 0; i < 4; i++) {
        const int q = i * 256 + tid;
        const float2 gg = g2[q], bb = b2[q];
        orow[q] = make_float2((v[i].x - mean) * rstd * gg.x + bb.x,
                              (v[i].y - mean) * rstd * gg.y + bb.y);
    }
}

// ---------------- launch: forked-stream overlapped schedule ------------------
extern "C" void kernel_launch(void* const* d_in, const int* in_sizes, int n_in,
                              void* d_out, int out_size) {
    const float* x     = (const float*)d_in[0];
    const float* Wp    = (const float*)d_in[5];
    const float* bp    = (const float*)d_in[6];
    const float* gamma = (const float*)d_in[7];
    const float* beta  = (const float*)d_in[8];
    float* out = (float*)d_out;

    static bool init_done = false;
    static cudaStream_t s2 = nullptr;
    static cudaEvent_t evCvtLo, evCvtHi, evGemmLo, evLnLo;
    if (!init_done) {
        cudaFuncSetAttribute(gemm_hmma_kernel,
                             cudaFuncAttributeMaxDynamicSharedMemorySize, hg::SMEM_BYTES);
        cudaStreamCreateWithFlags(&s2, cudaStreamNonBlocking);
        cudaEventCreateWithFlags(&evCvtLo,  cudaEventDisableTiming);
        cudaEventCreateWithFlags(&evCvtHi,  cudaEventDisableTiming);
        cudaEventCreateWithFlags(&evGemmLo, cudaEventDisableTiming);
        cudaEventCreateWithFlags(&evLnLo,   cudaEventDisableTiming);
        init_done = true;
    }

    __half* gA; cudaGetSymbolAddress((void**)&gA, g_A);
    __half* gB; cudaGetSymbolAddress((void**)&gB, g_B);

    const int xlo8 = R_LO * D_DIM / 8;                 // x rows [0, R_LO)
    const int xhi8 = (M_DIM - R_LO) * D_DIM / 8;       // x rows [R_LO, M)
    const int nw8  = D_DIM * D_DIM / 8;
    const int ntot_lo = xlo8 + nw8;

    // s0: convert x_lo + all W
    cvt_fp16_kernel<<<(ntot_lo + 255) / 256, 256>>>(
        (const float4*)x, (const float4*)Wp, (uint4*)gA, (uint4*)gB, xlo8, ntot_lo);
    cudaEventRecord(evCvtLo, 0);

    // s2: convert x_hi (overlaps gemm_lo)
    cudaStreamWaitEvent(s2, evCvtLo, 0);
    cvt_x_range_kernel<<<(xhi8 + 255) / 256, 256, 0, s2>>>(
        (const float4*)x + (size_t)R_LO * D_DIM / 4,
        (uint4*)gA + (size_t)R_LO * D_DIM / 8, xhi8);
    cudaEventRecord(evCvtHi, s2);

    // s0: gemm_lo (rows [0, R_LO)) — 1184 CTAs = exactly 4 waves
    gemm_hmma_kernel<<<dim3(D_DIM / hg::BN, YBLK_LO), 128, hg::SMEM_BYTES>>>(bp, 0);
    cudaEventRecord(evGemmLo, 0);

    // s0: gemm_hi (rows [R_LO, M)) — needs x_hi converted
    cudaStreamWaitEvent(0, evCvtHi, 0);
    gemm_hmma_kernel<<<dim3(D_DIM / hg::BN, YBLK_HI), 128, hg::SMEM_BYTES>>>(bp, YBLK_LO);

    // s2: ln_lo (rows [0, LN_LO)) — depends only on gemm_lo; overlaps gemm_hi
    cudaStreamWaitEvent(s2, evGemmLo, 0);
    ln_fuse_kernel<<<LN_LO, 256, 0, s2>>>(x, gamma, beta, out, 0);
    cudaEventRecord(evLnLo, s2);

    // s0: ln_hi (rows [LN_LO, M)) — after gemm_hi (stream order)
    ln_fuse_kernel<<<LN_HI, 256>>>(x, gamma, beta, out, LN_LO);

    // join forked work back into the capture-origin stream
    cudaStreamWaitEvent(0, evLnLo, 0);
}

// round 17
// speedup vs baseline: 1.0771x; 1.0316x over previous
#include <cuda_runtime.h>
#include <cuda_fp16.h>
#include <cstdint>

#define B_DIM 8
#define T_DIM 2048
#define D_DIM 2048
#define M_DIM (B_DIM * T_DIM)   // 16384

// Wave-aligned GEMM chunks: 148 SMs x 2 CTAs = 296 slots; 37*16 = 592 = 2 waves.
#define YC0 37
#define YC1 37
#define YC2 (128 - YC0 - YC1)             // 54
#define R0E (YC0 * 128)                   // 4736
#define R1E ((YC0 + YC1) * 128)           // 9472
#define LN_LO (R1E - 1)                   // 9471 rows: need P < R1E only
#define LN_HI (M_DIM - LN_LO)             // 6913

// ---------------- device-global scratch (static, allowed) -------------------
__device__ __align__(256) __half g_Ph[(size_t)M_DIM * D_DIM];  // (x@Wp^T+bp)/6, fp16
__device__ __align__(256) __half g_A [(size_t)M_DIM * D_DIM];  // fp16(x)
__device__ __align__(256) __half g_B [(size_t)D_DIM * D_DIM];  // fp16(Wp)

// ---------------- helpers ----------------------------------------------------
__device__ __forceinline__ uint32_t smem_u32(const void* p) {
    uint32_t a;
    asm("{ .reg .u64 t; cvta.to.shared.u64 t, %1; cvt.u32.u64 %0, t; }" : "=r"(a) : "l"(p));
    return a;
}
__device__ __forceinline__ void cp16(uint32_t sdst, const void* gsrc) {
    asm volatile("cp.async.cg.shared.global [%0], [%1], 16;" :: "r"(sdst), "l"(gsrc));
}
__device__ __forceinline__ uint32_t sw128(uint32_t o) { return o ^ ((o >> 3) & 0x70); }

__device__ __forceinline__ void ldmatrix_x4(uint32_t* f, uint32_t addr) {
    asm volatile("ldmatrix.sync.aligned.m8n8.x4.shared.b16 {%0,%1,%2,%3}, [%4];"
                 : "=r"(f[0]), "=r"(f[1]), "=r"(f[2]), "=r"(f[3]) : "r"(addr));
}
__device__ __forceinline__ void mma16816(float* c, const uint32_t* a,
                                         uint32_t b0, uint32_t b1) {
    asm volatile(
        "mma.sync.aligned.m16n8k16.row.col.f32.f16.f16.f32 "
        "{%0,%1,%2,%3}, {%4,%5,%6,%7}, {%8,%9}, {%0,%1,%2,%3};"
        : "+f"(c[0]), "+f"(c[1]), "+f"(c[2]), "+f"(c[3])
        : "r"(a[0]), "r"(a[1]), "r"(a[2]), "r"(a[3]), "r"(b0), "r"(b1));
}

// ---------------- fp32 -> fp16 converts --------------------------------------
// chunk A: x rows [0, R0E) plus all of Wp (one fused launch)
__global__ __launch_bounds__(256) void cvt_fp16_kernel(
    const float4* __restrict__ xs, const float4* __restrict__ ws,
    uint4* __restrict__ da, uint4* __restrict__ db, int nx8, int ntot8) {
    int i = blockIdx.x * 256 + threadIdx.x;
    if (i >= ntot8) return;
    const bool isx = (i < nx8);
    const float4* src = isx ? (xs + 2 * (size_t)i) : (ws + 2 * (size_t)(i - nx8));
    const float4 v0 = src[0];
    const float4 v1 = src[1];
    __half2 h0 = __floats2half2_rn(v0.x, v0.y);
    __half2 h1 = __floats2half2_rn(v0.z, v0.w);
    __half2 h2 = __floats2half2_rn(v1.x, v1.y);
    __half2 h3 = __floats2half2_rn(v1.z, v1.w);
    uint4 o = make_uint4(*reinterpret_cast<const uint32_t*>(&h0),
                         *reinterpret_cast<const uint32_t*>(&h1),
                         *reinterpret_cast<const uint32_t*>(&h2),
                         *reinterpret_cast<const uint32_t*>(&h3));
    if (isx) da[i] = o; else db[i - nx8] = o;
}

// chunks B/C: a row-range of x only
__global__ __launch_bounds__(256) void cvt_x_range_kernel(
    const float4* __restrict__ xs, uint4* __restrict__ da, int n8) {
    int i = blockIdx.x * 256 + threadIdx.x;
    if (i >= n8) return;
    const float4 v0 = xs[2 * (size_t)i];
    const float4 v1 = xs[2 * (size_t)i + 1];
    __half2 h0 = __floats2half2_rn(v0.x, v0.y);
    __half2 h1 = __floats2half2_rn(v0.z, v0.w);
    __half2 h2 = __floats2half2_rn(v1.x, v1.y);
    __half2 h3 = __floats2half2_rn(v1.z, v1.w);
    da[i] = make_uint4(*reinterpret_cast<const uint32_t*>(&h0),
                       *reinterpret_cast<const uint32_t*>(&h1),
                       *reinterpret_cast<const uint32_t*>(&h2),
                       *reinterpret_cast<const uint32_t*>(&h3));
}

// ---------------- HMMA GEMM (R14 proven schedule + y-offset) -----------------
namespace hg {
constexpr int BM = 128, BN = 128, BK = 64, STAGES = 3;
constexpr int NKT = D_DIM / BK;                 // 32
constexpr int TILE_A = BM * 128;                // 16 KB
constexpr int TILE_B = BN * 128;                // 16 KB
constexpr int SMEM_BYTES = STAGES * (TILE_A + TILE_B) + 1024;  // 99328
}

__global__ __launch_bounds__(128, 2) void gemm_hmma_kernel(
    const float* __restrict__ bias, int y0) {
    using namespace hg;
    extern __shared__ char smem_raw[];
    const uint32_t sbase = (smem_u32(smem_raw) + 1023u) & ~1023u;
    const uint32_t bbase = sbase + STAGES * TILE_A;

    const int tid  = threadIdx.x;
    const int wid  = tid >> 5;
    const int lane = tid & 31;
    const int brow = (blockIdx.y + y0) * BM;
    const int bcol = blockIdx.x * BN;
    const int wm = wid & 1;
    const int wn = wid >> 1;

    const __half* Ag = g_A + (size_t)brow * D_DIM;
    const __half* Bg = g_B + (size_t)bcol * D_DIM;

    const int lrow = tid >> 3;   // 0..15
    const int lseg = tid & 7;

    auto load_stage = [&](int s, int k0) {
        const uint32_t a_s = sbase + s * TILE_A;
        const uint32_t b_s = bbase + s * TILE_B;
#pragma unroll
        for (int p = 0; p < 8; p++) {
            const int row = lrow + p * 16;
            const uint32_t off = sw128((uint32_t)(row * 128 + lseg * 16));
            const size_t gofs = (size_t)row * D_DIM + k0 + lseg * 8;
            cp16(a_s + off, Ag + gofs);
            cp16(b_s + off, Bg + gofs);
        }
    };

    const int a_r_base = wm * 64 + (lane & 15);
    const int ab_cb    = ((lane >> 4) << 4);
    const int b_r_base = wn * 64 + (lane & 7) + ((lane >> 3) & 1) * 8;

    auto load_frags = [&](uint32_t (&af)[4][4], uint32_t (&bf)[4][4],
                          int s, int kb) {
        const uint32_t a_s = sbase + s * TILE_A;
        const uint32_t b_s = bbase + s * TILE_B;
#pragma unroll
        for (int i = 0; i < 4; i++)
            ldmatrix_x4(af[i], a_s + sw128((uint32_t)((a_r_base + i * 16) * 128 + kb + ab_cb)));
#pragma unroll
        for (int j = 0; j < 4; j++)
            ldmatrix_x4(bf[j], b_s + sw128((uint32_t)((b_r_base + j * 16) * 128 + kb + ab_cb)));
    };

    float acc[4][8][4];
#pragma unroll
    for (int i = 0; i < 4; i++)
#pragma unroll
        for (int j = 0; j < 8; j++)
#pragma unroll
            for (int e = 0; e < 4; e++) acc[i][j][e] = 0.0f;

    auto mma_all = [&](uint32_t (&af)[4][4], uint32_t (&bf)[4][4]) {
#pragma unroll
        for (int i = 0; i < 4; i++)
#pragma unroll
            for (int j = 0; j < 4; j++) {
                mma16816(acc[i][2 * j],     af[i], bf[j][0], bf[j][2]);
                mma16816(acc[i][2 * j + 1], af[i], bf[j][1], bf[j][3]);
            }
    };

    load_stage(0, 0);
    asm volatile("cp.async.commit_group;" ::: "memory");
    load_stage(1, BK);
    asm volatile("cp.async.commit_group;" ::: "memory");
    asm volatile("cp.async.wait_group 1;" ::: "memory");
    __syncthreads();

    uint32_t af[2][4][4], bf[2][4][4];
    load_frags(af[0], bf[0], 0, 0);

#define KT_BODY(S, SLD, SNXT, KT)                                             \
    {                                                                         \
        const int pf = (KT) + 2;                                              \
        if (pf < NKT) load_stage((SLD), pf * BK);                             \
        asm volatile("cp.async.commit_group;" ::: "memory");                  \
        _Pragma("unroll")                                                     \
        for (int kk = 0; kk < BK / 16; kk++) {                                \
            const int cur = kk & 1, nxt = cur ^ 1;                            \
            if (kk < 3) {                                                     \
                load_frags(af[nxt], bf[nxt], (S), (kk + 1) * 32);             \
            } else if ((KT) + 1 < NKT) {                                      \
                asm volatile("cp.async.wait_group 1;" ::: "memory");          \
                load_frags(af[nxt], bf[nxt], (SNXT), 0);                      \
            }                                                                 \
            mma_all(af[cur], bf[cur]);                                        \
        }                                                                     \
        __syncthreads();                                                      \
    }

#pragma unroll 1
    for (int ktg = 0; ktg < NKT - 2; ktg += 3) {
        KT_BODY(0, 2, 1, ktg);
        KT_BODY(1, 0, 2, ktg + 1);
        KT_BODY(2, 1, 0, ktg + 2);
    }
    KT_BODY(0, 2, 1, NKT - 2);
    KT_BODY(1, 0, 2, NKT - 1);
#undef KT_BODY

    const float inv6 = 1.0f / 6.0f;
    const int prow0 = brow + wm * 64 + (lane >> 2);
    const int pcol0 = bcol + wn * 64 + (lane & 3) * 2;
#pragma unroll
    for (int i = 0; i < 4; i++) {
        const size_t r0 = (size_t)(prow0 + i * 16);
#pragma unroll
        for (int j = 0; j < 8; j++) {
            const int c = pcol0 + j * 8;
            const float b0 = bias[c], b1 = bias[c + 1];
            __half2 lo = __floats2half2_rn((acc[i][j][0] + b0) * inv6,
                                           (acc[i][j][1] + b1) * inv6);
            __half2 hi = __floats2half2_rn((acc[i][j][2] + b0) * inv6,
                                           (acc[i][j][3] + b1) * inv6);
            *reinterpret_cast<__half2*>(&g_Ph[r0 * D_DIM + c])       = lo;
            *reinterpret_cast<__half2*>(&g_Ph[(r0 + 8) * D_DIM + c]) = hi;
        }
    }
}

// ---------------- fused chained LayerNorm (pinned: 256 thr, float2) ----------
__device__ __forceinline__ float2 block_sum2(float a, float b) {
    __shared__ float sm[16];
    const int lane = threadIdx.x & 31;
    const int wid  = threadIdx.x >> 5;
#pragma unroll
    for (int o = 16; o > 0; o >>= 1) {
        a += __shfl_xor_sync(0xffffffffu, a, o);
        b += __shfl_xor_sync(0xffffffffu, b, o);
    }
    __syncthreads();
    if (lane == 0) { sm[wid] = a; sm[8 + wid] = b; }
    __syncthreads();
    float sa = 0.0f, sb = 0.0f;
#pragma unroll
    for (int i = 0; i < 8; i++) { sa += sm[i]; sb += sm[8 + i]; }
    return make_float2(sa, sb);
}

__global__ __launch_bounds__(256) void ln_fuse_kernel(
    const float* __restrict__ x, const float* __restrict__ gamma,
    const float* __restrict__ beta, float* __restrict__ out, int r0) {
    const int r   = blockIdx.x + r0;
    const int t   = r & (T_DIM - 1);
    const int tid = threadIdx.x;
    const float invD = 1.0f / (float)D_DIM;
    constexpr int DP = D_DIM / 2;

    const float2*  xr = (const float2*)x + (size_t)r * DP;
    const int p1row   = (t == 0) ? (r + 1) : (r - 1);
    const __half2* p1 = (const __half2*)g_Ph + (size_t)p1row * DP;
    const float2*  g2 = (const float2*)gamma;
    const float2*  b2 = (const float2*)beta;

    float2 v[4];
    float s = 0.0f, sq = 0.0f;
#pragma unroll
    for (int i = 0; i < 4; i++) {
        const int q = i * 256 + tid;
        const float2 xv = xr[q];
        const float2 pv = __half22float2(p1[q]);
        const float a = xv.x + pv.x, b = xv.y + pv.y;
        v[i] = make_float2(a, b);
        s += a + b; sq += a * a + b * b;
    }
    float2 red = block_sum2(s, sq);
    float mean = red.x * invD;
    float var  = red.y * invD - mean * mean;
    float rstd = rsqrtf(var + 1e-5f);

    if (t >= 1 && t <= T_DIM - 2) {
        const __half2* p2 = (const __half2*)g_Ph + (size_t)(r + 1) * DP;
        s = 0.0f; sq = 0.0f;
#pragma unroll
        for (int i = 0; i < 4; i++) {
            const int q = i * 256 + tid;
            const float2 gg = g2[q], bb = b2[q];
            const float2 pv = __half22float2(p2[q]);
            const float a = (v[i].x - mean) * rstd * gg.x + bb.x + pv.x;
            const float b = (v[i].y - mean) * rstd * gg.y + bb.y + pv.y;
            v[i] = make_float2(a, b);
            s += a + b; sq += a * a + b * b;
        }
        red  = block_sum2(s, sq);
        mean = red.x * invD;
        var  = red.y * invD - mean * mean;
        rstd = rsqrtf(var + 1e-5f);
    }

    float2* orow = (float2*)out + (size_t)r * DP;
#pragma unroll
    for (int i = 0; i < 4; i++) {
        const int q = i * 256 + tid;
        const float2 gg = g2[q], bb = b2[q];
        orow[q] = make_float2((v[i].x - mean) * rstd * gg.x + bb.x,
                              (v[i].y - mean) * rstd * gg.y + bb.y);
    }
}

// ---------------- launch: 3-way drainless pipelined schedule -----------------
extern "C" void kernel_launch(void* const* d_in, const int* in_sizes, int n_in,
                              void* d_out, int out_size) {
    const float* x     = (const float*)d_in[0];
    const float* Wp    = (const float*)d_in[5];
    const float* bp    = (const float*)d_in[6];
    const float* gamma = (const float*)d_in[7];
    const float* beta  = (const float*)d_in[8];
    float* out = (float*)d_out;

    static bool init_done = false;
    static cudaStream_t s2 = nullptr, s3 = nullptr;
    static cudaEvent_t evA, evB, evG0, evG1, evG2, evLnLo;
    if (!init_done) {
        cudaFuncSetAttribute(gemm_hmma_kernel,
                             cudaFuncAttributeMaxDynamicSharedMemorySize, hg::SMEM_BYTES);
        cudaStreamCreateWithFlags(&s2, cudaStreamNonBlocking);
        cudaStreamCreateWithFlags(&s3, cudaStreamNonBlocking);
        cudaEventCreateWithFlags(&evA,    cudaEventDisableTiming);
        cudaEventCreateWithFlags(&evB,    cudaEventDisableTiming);
        cudaEventCreateWithFlags(&evG0,   cudaEventDisableTiming);
        cudaEventCreateWithFlags(&evG1,   cudaEventDisableTiming);
        cudaEventCreateWithFlags(&evG2,   cudaEventDisableTiming);
        cudaEventCreateWithFlags(&evLnLo, cudaEventDisableTiming);
        init_done = true;
    }

    __half* gA; cudaGetSymbolAddress((void**)&gA, g_A);
    __half* gB; cudaGetSymbolAddress((void**)&gB, g_B);

    const int c0_8 = R0E * D_DIM / 8;                 // x rows [0, R0E)
    const int c1_8 = (R1E - R0E) * D_DIM / 8;         // x rows [R0E, R1E)
    const int c2_8 = (M_DIM - R1E) * D_DIM / 8;       // x rows [R1E, M)
    const int nw8  = D_DIM * D_DIM / 8;
    const int ntotA = c0_8 + nw8;

    // chunk A (s0): x[0, R0E) + all W
    cvt_fp16_kernel<<<(ntotA + 255) / 256, 256>>>(
        (const float4*)x, (const float4*)Wp, (uint4*)gA, (uint4*)gB, c0_8, ntotA);
    cudaEventRecord(evA, 0);

    // chunk B (s2): x[R0E, R1E)  — hides under gemm0
    cudaStreamWaitEvent(s2, evA, 0);
    cvt_x_range_kernel<<<(c1_8 + 255) / 256, 256, 0, s2>>>(
        (const float4*)x + (size_t)R0E * D_DIM / 4,
        (uint4*)gA + (size_t)R0E * D_DIM / 8, c1_8);
    cudaEventRecord(evB, s2);

    // chunk C (s3): x[R1E, M)  — hides under gemm0/gemm1
    cudaStreamWaitEvent(s3, evB, 0);
    cvt_x_range_kernel<<<(c2_8 + 255) / 256, 256, 0, s3>>>(
        (const float4*)x + (size_t)R1E * D_DIM / 4,
        (uint4*)gA + (size_t)R1E * D_DIM / 8, c2_8);

    // gemm chunks on three streams: mutually independent -> drainless hand-off
    gemm_hmma_kernel<<<dim3(D_DIM / hg::BN, YC0), 128, hg::SMEM_BYTES>>>(bp, 0);
    cudaEventRecord(evG0, 0);
    gemm_hmma_kernel<<<dim3(D_DIM / hg::BN, YC1), 128, hg::SMEM_BYTES, s2>>>(bp, YC0);
    cudaEventRecord(evG1, s2);
    gemm_hmma_kernel<<<dim3(D_DIM / hg::BN, YC2), 128, hg::SMEM_BYTES, s3>>>(bp, YC0 + YC1);
    cudaEventRecord(evG2, s3);

    // ln_lo (rows [0, LN_LO)) needs P rows < R1E: gemm0 (event) + gemm1 (stream order)
    cudaStreamWaitEvent(s2, evG0, 0);
    ln_fuse_kernel<<<LN_LO, 256, 0, s2>>>(x, gamma, beta, out, 0);
    cudaEventRecord(evLnLo, s2);

    // ln_hi (rows [LN_LO, M)) needs gemm1 + gemm2 (gemm0 implied by s0 order)
    cudaStreamWaitEvent(0, evG1, 0);
    cudaStreamWaitEvent(0, evG2, 0);
    ln_fuse_kernel<<<LN_HI, 256>>>(x, gamma, beta, out, LN_LO);

    // join forked work back into the capture-origin stream
    cudaStreamWaitEvent(0, evLnLo, 0);
}